// round 11
// baseline (speedup 1.0000x reference)
#include <cuda_runtime.h>
#include <math.h>
#include <stdint.h>

#define T_  4096
#define D_  1024
#define S_  4
#define TB_ 1024
#define WB_ 256
#define NB_ 16

#define MT 128
#define NT 128
#define KC 32
#define THREADS 256
#define TW2 40                      // interleaved row stride in words (32 data + 8 pad)
#define TILE2W (128 * TW2)          // 5120 words per operand tile
#define STAGE2W (2 * TILE2W)        // A + B
#define SMEM_DYN (2 * STAGE2W * 4)  // 81920 bytes

// ---------------- scratch (identical to R10 passing kernel) ------------------
__device__ float g_xu[T_ * D_];
__device__ float g_div[S_][TB_ * TB_];
__device__ float g_Q[T_ * D_];
__device__ float g_K[T_ * D_];
__device__ float g_V[T_ * D_];
__device__ float g_Vt[NB_][WB_ * TB_];   // V block transposed [n][k], (1+dep) folded
__device__ float g_AP[TB_ * TB_];
__device__ float g_attw[NB_][TB_ * TB_];
__device__ float g_ent[NB_][TB_];
__device__ float g_dep[NB_][TB_];
__device__ float g_ctx[NB_][TB_ * WB_];
__device__ float g_y[T_ * D_];
__device__ float g_W2[WB_ * WB_];
__device__ float g_w2e[WB_];
__device__ float g_w2d[WB_];

// ---------------- helpers ----------------------------------------------------
__device__ __forceinline__ void bsplit(float x0, float x1, uint32_t& hi, uint32_t& lo) {
    uint32_t h;
    asm("cvt.rn.bf16x2.f32 %0, %1, %2;" : "=r"(h) : "f"(x1), "f"(x0));
    float f0 = __uint_as_float(h << 16);
    float f1 = __uint_as_float(h & 0xFFFF0000u);
    float r0 = x0 - f0, r1 = x1 - f1;
    uint32_t l;
    asm("cvt.rn.bf16x2.f32 %0, %1, %2;" : "=r"(l) : "f"(r1), "f"(r0));
    hi = h; lo = l;
}

__device__ __forceinline__ void mma_bf16(float c[4], const uint32_t a[4],
                                         const uint32_t b[2]) {
    asm volatile(
        "mma.sync.aligned.m16n8k16.row.col.f32.bf16.bf16.f32 "
        "{%0,%1,%2,%3}, {%4,%5,%6,%7}, {%8,%9}, {%0,%1,%2,%3};"
        : "+f"(c[0]), "+f"(c[1]), "+f"(c[2]), "+f"(c[3])
        : "r"(a[0]), "r"(a[1]), "r"(a[2]), "r"(a[3]), "r"(b[0]), "r"(b[1]));
}

__device__ __forceinline__ float warpSum(float v) {
    #pragma unroll
    for (int o = 16; o; o >>= 1) v += __shfl_xor_sync(0xffffffffu, v, o);
    return v;
}
__device__ __forceinline__ float warpMax(float v) {
    #pragma unroll
    for (int o = 16; o; o >>= 1) v = fmaxf(v, __shfl_xor_sync(0xffffffffu, v, o));
    return v;
}
template <bool ISMAX>
__device__ __forceinline__ float blockReduce(float v) {
    __shared__ float sh[8];
    int lane = threadIdx.x & 31, w = threadIdx.x >> 5;
    v = ISMAX ? warpMax(v) : warpSum(v);
    if (lane == 0) sh[w] = v;
    __syncthreads();
    if (w == 0) {
        float t = (lane < 8) ? sh[lane] : (ISMAX ? -INFINITY : 0.0f);
        t = ISMAX ? warpMax(t) : warpSum(t);
        if (lane == 0) sh[0] = t;
    }
    __syncthreads();
    float r = sh[0];
    __syncthreads();
    return r;
}

// frag buffers for one s16 phase
struct Frag {
    uint32_t ah[4][4], al[4][4], bh[4][2], bl[4][2];
};

__device__ __forceinline__ void load_frags(const uint32_t* __restrict__ As,
                                           const uint32_t* __restrict__ Bs,
                                           int s16, int wr, int wc, int gid, int t4,
                                           Frag& f) {
    const int k0 = 2 * (s16 * 8 + t4);    // word offset of kpair
    const int k1 = k0 + 8;                // +4 kpairs
    #pragma unroll
    for (int mi = 0; mi < 4; mi++) {
        const int r0 = (wr * 64 + mi * 16 + gid) * TW2;
        const int r8 = r0 + 8 * TW2;
        uint2 v;
        v = *(const uint2*)(As + r0 + k0); f.ah[mi][0] = v.x; f.al[mi][0] = v.y;
        v = *(const uint2*)(As + r8 + k0); f.ah[mi][1] = v.x; f.al[mi][1] = v.y;
        v = *(const uint2*)(As + r0 + k1); f.ah[mi][2] = v.x; f.al[mi][2] = v.y;
        v = *(const uint2*)(As + r8 + k1); f.ah[mi][3] = v.x; f.al[mi][3] = v.y;
    }
    #pragma unroll
    for (int ni = 0; ni < 4; ni++) {
        const int nr = (wc * 32 + ni * 8 + gid) * TW2;
        uint2 v;
        v = *(const uint2*)(Bs + nr + k0); f.bh[ni][0] = v.x; f.bl[ni][0] = v.y;
        v = *(const uint2*)(Bs + nr + k1); f.bh[ni][1] = v.x; f.bl[ni][1] = v.y;
    }
}

__device__ __forceinline__ void mma_frags(float acc[4][4][4], const Frag& f) {
    #pragma unroll
    for (int mi = 0; mi < 4; mi++)
        #pragma unroll
        for (int ni = 0; ni < 4; ni++) {
            mma_bf16(acc[mi][ni], f.ah[mi], f.bl[ni]);
            mma_bf16(acc[mi][ni], f.al[mi], f.bh[ni]);
            mma_bf16(acc[mi][ni], f.ah[mi], f.bh[ni]);
        }
}

// ------- bf16x3 mma.sync GEMM, fp32 in/out (NT, 128x128 CTA, 64x32 warp) -----
enum { M_DIV = 0, M_Q = 1, M_K = 2, M_V = 3, M_SIM = 4, M_CTX = 5, M_OUT2 = 6, M_FIN = 7 };

__global__ void __launch_bounds__(THREADS, 1)
k_mma(int mode, const float* __restrict__ pA, const float* __restrict__ pB,
      float* __restrict__ pC) {
    extern __shared__ uint32_t sm[];
    const int tid = threadIdx.x, w = tid >> 5, lane = tid & 31;
    const int wr = w >> 2, wc = w & 3;              // warp grid 2x4
    const int gid = lane >> 2, t4 = lane & 3;       // fragment coords

    // ---- per-mode problem setup (identical to R10) ----
    const float *A, *B;
    float* C = nullptr;
    int K, lda, ldb, ldc = 0;
    const int z = blockIdx.z, bi = z >> 2, bj = z & 3;
    switch (mode) {
        case M_DIV:
            A = g_xu + (size_t)z * TB_ * D_; B = A;
            C = g_div[z]; K = D_; lda = ldb = D_; ldc = TB_; break;
        case M_Q: case M_K: case M_V:
            A = pA; B = pB;
            C = (mode == M_Q) ? g_Q : (mode == M_K) ? g_K : g_V;
            K = D_; lda = ldb = D_; ldc = D_; break;
        case M_SIM:
            A = g_Q + (size_t)(bi * TB_) * D_ + bj * WB_;
            B = g_K + (size_t)(bi * TB_) * D_ + bj * WB_;
            C = g_attw[z]; K = WB_; lda = ldb = D_; ldc = TB_; break;
        case M_CTX:
            A = g_attw[z]; B = g_Vt[z];
            C = g_ctx[z]; K = TB_; lda = TB_; ldb = TB_; ldc = WB_; break;
        case M_OUT2:
            A = g_ctx[z]; B = g_W2;
            K = WB_; lda = WB_; ldb = WB_; break;
        default: // M_FIN
            A = g_y; B = pB; C = pC; K = D_; lda = ldb = D_; ldc = D_; break;
    }
    const int m0 = blockIdx.y * MT, n0 = blockIdx.x * NT;
    A += (size_t)m0 * lda;
    B += (size_t)n0 * ldb;

    // ---- loader mapping: 4 float4 per operand per chunk ----
    const float* pa[4];
    const float* pb[4];
    int soff[4];
    #pragma unroll
    for (int p = 0; p < 4; p++) {
        int pos = tid + p * THREADS;        // 0..1023
        int r = pos >> 3, c4 = (pos & 7) << 2;
        soff[p] = r * TW2 + c4;             // interleaved: word == float col
        pa[p] = A + (size_t)r * lda + c4;
        pb[p] = B + (size_t)r * ldb + c4;
    }

    float acc[4][4][4] = {};
    const int nChunks = K / KC;

    float4 ra[4], rb[4];
    #pragma unroll
    for (int p = 0; p < 4; p++) { ra[p] = *(const float4*)(pa[p]); rb[p] = *(const float4*)(pb[p]); }

    // split + store stage 0: uint4 (h0,l0,h1,l1) covers kpairs c4/2, c4/2+1
    {
        uint32_t* b0 = sm;
        #pragma unroll
        for (int p = 0; p < 4; p++) {
            uint32_t h0, l0, h1, l1;
            bsplit(ra[p].x, ra[p].y, h0, l0);
            bsplit(ra[p].z, ra[p].w, h1, l1);
            *(uint4*)(b0 + soff[p]) = make_uint4(h0, l0, h1, l1);
            bsplit(rb[p].x, rb[p].y, h0, l0);
            bsplit(rb[p].z, rb[p].w, h1, l1);
            *(uint4*)(b0 + TILE2W + soff[p]) = make_uint4(h0, l0, h1, l1);
        }
    }
    __syncthreads();

    for (int ch = 0; ch < nChunks; ch++) {
        // gmem prefetch for next chunk (long-latency, issued first)
        if (ch + 1 < nChunks) {
            #pragma unroll
            for (int p = 0; p < 4; p++) {
                ra[p] = *(const float4*)(pa[p] + (ch + 1) * KC);
                rb[p] = *(const float4*)(pb[p] + (ch + 1) * KC);
            }
        }
        // compute from stage ch&1 with intra-chunk frag double-buffering:
        // load F0 and F1 up front, mma(F0) overlaps F1's LDS in flight
        {
            const uint32_t* base = sm + (ch & 1) * STAGE2W;
            const uint32_t* As = base;
            const uint32_t* Bs = base + TILE2W;
            Frag f0, f1;
            load_frags(As, Bs, 0, wr, wc, gid, t4, f0);
            load_frags(As, Bs, 1, wr, wc, gid, t4, f1);
            mma_frags(acc, f0);
            mma_frags(acc, f1);
        }
        if (ch + 1 < nChunks) {
            uint32_t* b0 = sm + ((ch + 1) & 1) * STAGE2W;
            #pragma unroll
            for (int p = 0; p < 4; p++) {
                uint32_t h0, l0, h1, l1;
                bsplit(ra[p].x, ra[p].y, h0, l0);
                bsplit(ra[p].z, ra[p].w, h1, l1);
                *(uint4*)(b0 + soff[p]) = make_uint4(h0, l0, h1, l1);
                bsplit(rb[p].x, rb[p].y, h0, l0);
                bsplit(rb[p].z, rb[p].w, h1, l1);
                *(uint4*)(b0 + TILE2W + soff[p]) = make_uint4(h0, l0, h1, l1);
            }
            __syncthreads();
        }
    }

    // ---- epilogue (identical to R10) ----
    #pragma unroll
    for (int mi = 0; mi < 4; mi++) {
        const int mr0 = m0 + wr * 64 + mi * 16 + gid;
        const int mr1 = mr0 + 8;
        float e0 = 0.f, e1 = 0.f, d0 = 0.f, d1 = 0.f;
        if (mode == M_OUT2) {
            e0 = g_ent[z][mr0]; e1 = g_ent[z][mr1];
            d0 = g_dep[z][mr0]; d1 = g_dep[z][mr1];
        }
        #pragma unroll
        for (int ni = 0; ni < 4; ni++) {
            const int nc = n0 + wc * 32 + ni * 8 + 2 * t4;
            float v00 = acc[mi][ni][0], v01 = acc[mi][ni][1];
            float v10 = acc[mi][ni][2], v11 = acc[mi][ni][3];
            if (mode == M_DIV) {
                v00 = 1.0f - v00; v01 = 1.0f - v01;
                v10 = 1.0f - v10; v11 = 1.0f - v11;
            } else if (mode == M_SIM) {
                v00 += g_AP[(size_t)mr0 * TB_ + nc];
                v01 += g_AP[(size_t)mr0 * TB_ + nc + 1];
                v10 += g_AP[(size_t)mr1 * TB_ + nc];
                v11 += g_AP[(size_t)mr1 * TB_ + nc + 1];
            }
            if (mode == M_OUT2) {
                const float we0 = g_w2e[nc], we1 = g_w2e[nc + 1];
                const float wd0 = g_w2d[nc], wd1 = g_w2d[nc + 1];
                float* y0 = g_y + (size_t)(bi * TB_ + mr0) * D_ + bj * WB_ + nc;
                float* y1 = g_y + (size_t)(bi * TB_ + mr1) * D_ + bj * WB_ + nc;
                y0[0] = v00 + e0 * we0 + d0 * wd0;
                y0[1] = v01 + e0 * we1 + d0 * wd1;
                y1[0] = v10 + e1 * we0 + d1 * wd0;
                y1[1] = v11 + e1 * we1 + d1 * wd1;
            } else {
                float* c0p = C + (size_t)mr0 * ldc + nc;
                float* c1p = C + (size_t)mr1 * ldc + nc;
                *(float2*)c0p = make_float2(v00, v01);
                *(float2*)c1p = make_float2(v10, v11);
            }
        }
    }
}

// ---------------- elementwise stage kernels (identical to R10) ---------------
__global__ void k_norm(const float* __restrict__ x) {
    int t = blockIdx.x, tid = threadIdx.x;
    const float* xp = x + (size_t)t * D_;
    float v = 0.0f;
    for (int j = tid; j < D_; j += 256) { float a = xp[j]; v += a * a; }
    v = blockReduce<false>(v);
    float inv = 1.0f / fmaxf(sqrtf(v), 1e-12f);
    for (int j = tid; j < D_; j += 256) g_xu[(size_t)t * D_ + j] = xp[j] * inv;
}

__global__ void k_ap() {
    int idx = blockIdx.x * 256 + threadIdx.x;
    int p = idx >> 10, c = idx & 1023;
    int ih = c >> 1;
    float ang = (float)p / powf(10000.0f, (2.0f * (float)ih) / 1024.0f);
    g_AP[idx] = (c & 1) ? cosf(ang) : sinf(ang);
}

__global__ void k_repack(const float* __restrict__ W2) {
    int idx = blockIdx.x * 256 + threadIdx.x;
    if (idx >= WB_ * (WB_ + 2)) return;
    int n = idx / (WB_ + 2), k = idx % (WB_ + 2);
    float v = W2[idx];
    if (k < WB_)       g_W2[n * WB_ + k] = v;
    else if (k == WB_) g_w2e[n] = v;
    else               g_w2d[n] = v;
}

__global__ void k_softmax() {
    int row = blockIdx.x;
    int b = row >> 10, q = row & 1023;
    int i = b >> 2;
    int tid = threadIdx.x;
    float* sp = g_attw[b] + (size_t)q * TB_;
    const float* dv = g_div[i] + (size_t)q * TB_;
    float s[4], d[4];
    #pragma unroll
    for (int j = 0; j < 4; j++) { s[j] = sp[tid + j * 256]; d[j] = dv[tid + j * 256]; }
    float mx = fmaxf(fmaxf(s[0], s[1]), fmaxf(s[2], s[3]));
    mx = blockReduce<true>(mx);
    float e[4], Z = 0.f, t = 0.f, ww = 0.f, ds = 0.f;
    #pragma unroll
    for (int j = 0; j < 4; j++) {
        e[j] = __expf(s[j] - mx);
        Z += e[j]; t += e[j] * (s[j] - mx); ww += d[j] * e[j]; ds += d[j];
    }
    Z = blockReduce<false>(Z);
    t = blockReduce<false>(t);
    ww = blockReduce<false>(ww);
    ds = blockReduce<false>(ds);
    float invZ = 1.0f / Z;
    #pragma unroll
    for (int j = 0; j < 4; j++) sp[tid + j * 256] = e[j] * invZ;
    if (tid == 0) {
        g_ent[b][q] = (logf(Z) - t * invZ) * (1.0f / 6.931471805599453f);
        g_dep[b][q] = (ww * invZ) / ds;
    }
}

__global__ void k_entnorm() {
    int b = blockIdx.x, tid = threadIdx.x;
    float v = 0.0f;
    for (int j = tid; j < TB_; j += 256) v += fabsf(g_ent[b][j]);
    v = blockReduce<false>(v);
    float inv = 1.0f / fmaxf(v, 1e-12f);
    for (int j = tid; j < TB_; j += 256) g_ent[b][j] *= inv;
}

// Vt[b][n][k] = V[(i*TB+k)*D + j*WB+n] * (1 + dep[b][k])
__global__ void k_vt() {
    __shared__ float tile[32][33];
    int b = blockIdx.z, i = b >> 2, j = b & 3;
    int k0 = blockIdx.x * 32, n0 = blockIdx.y * 32;
    int tx = threadIdx.x, ty = threadIdx.y;    // 32 x 8
    #pragma unroll
    for (int dy = 0; dy < 4; dy++) {
        int k = k0 + ty + dy * 8;
        int n = n0 + tx;
        tile[ty + dy * 8][tx] =
            g_V[(size_t)(i * TB_ + k) * D_ + j * WB_ + n] * (1.0f + g_dep[b][k]);
    }
    __syncthreads();
    #pragma unroll
    for (int dy = 0; dy < 4; dy++) {
        int n = n0 + ty + dy * 8;
        int k = k0 + tx;
        g_Vt[b][(size_t)n * TB_ + k] = tile[tx][ty + dy * 8];
    }
}

// ---------------- launch (identical to R10) ----------------------------------
extern "C" void kernel_launch(void* const* d_in, const int* in_sizes, int n_in,
                              void* d_out, int out_size) {
    const float* x    = (const float*)d_in[0];
    const float* Wq   = (const float*)d_in[1];
    const float* Wk   = (const float*)d_in[2];
    const float* Wv   = (const float*)d_in[3];
    const float* Wout = (const float*)d_in[4];
    const float* W2   = (const float*)d_in[5];
    float* out = (float*)d_out;

    cudaFuncSetAttribute(k_mma, cudaFuncAttributeMaxDynamicSharedMemorySize, SMEM_DYN);

    k_norm<<<T_, 256>>>(x);
    k_ap<<<(TB_ * TB_) / 256, 256>>>();
    k_repack<<<(WB_ * (WB_ + 2) + 255) / 256, 256>>>(W2);

    k_mma<<<dim3(TB_ / NT, TB_ / MT, S_), THREADS, SMEM_DYN>>>(M_DIV, nullptr, nullptr, nullptr);

    k_mma<<<dim3(D_ / NT, T_ / MT, 1), THREADS, SMEM_DYN>>>(M_Q, x, Wq, nullptr);
    k_mma<<<dim3(D_ / NT, T_ / MT, 1), THREADS, SMEM_DYN>>>(M_K, x, Wk, nullptr);
    k_mma<<<dim3(D_ / NT, T_ / MT, 1), THREADS, SMEM_DYN>>>(M_V, x, Wv, nullptr);

    k_mma<<<dim3(TB_ / NT, TB_ / MT, NB_), THREADS, SMEM_DYN>>>(M_SIM, nullptr, nullptr, nullptr);

    k_softmax<<<NB_ * TB_, 256>>>();
    k_entnorm<<<NB_, 256>>>();
    k_vt<<<dim3(TB_ / 32, WB_ / 32, NB_), dim3(32, 8)>>>();

    k_mma<<<dim3(WB_ / NT, TB_ / MT, NB_), THREADS, SMEM_DYN>>>(M_CTX, nullptr, nullptr, nullptr);
    k_mma<<<dim3(WB_ / NT, TB_ / MT, NB_), THREADS, SMEM_DYN>>>(M_OUT2, nullptr, nullptr, nullptr);
    k_mma<<<dim3(D_ / NT, T_ / MT, 1), THREADS, SMEM_DYN>>>(M_FIN, nullptr, Wout, out);
}

// round 12
// speedup vs baseline: 1.3206x; 1.3206x over previous
#include <cuda_runtime.h>
#include <math.h>
#include <stdint.h>

#define T_  4096
#define D_  1024
#define S_  4
#define TB_ 1024
#define WB_ 256
#define NB_ 16

#define MT 128
#define NT 128
#define KC 32
#define THREADS 256
#define TW 20                      // smem words per row (16 data + 4 pad)
#define TILEW (128 * TW)           // 2560 words per tile
#define STAGEW (4 * TILEW)         // Ah, Al, Bh, Bl
#define SMEM_DYN (2 * STAGEW * 4)  // 81920 bytes

// ---------------- scratch (identical to R10 passing kernel) ------------------
__device__ float g_xu[T_ * D_];
__device__ float g_div[S_][TB_ * TB_];
__device__ float g_Q[T_ * D_];
__device__ float g_K[T_ * D_];
__device__ float g_V[T_ * D_];
__device__ float g_Vt[NB_][WB_ * TB_];   // V block transposed [n][k], (1+dep) folded
__device__ float g_AP[TB_ * TB_];
__device__ float g_attw[NB_][TB_ * TB_];
__device__ float g_ent[NB_][TB_];
__device__ float g_dep[NB_][TB_];
__device__ float g_ctx[NB_][TB_ * WB_];
__device__ float g_y[T_ * D_];
__device__ float g_W2[WB_ * WB_];
__device__ float g_w2e[WB_];
__device__ float g_w2d[WB_];

// ---------------- helpers ----------------------------------------------------
__device__ __forceinline__ void bsplit(float x0, float x1, uint32_t& hi, uint32_t& lo) {
    uint32_t h;
    asm("cvt.rn.bf16x2.f32 %0, %1, %2;" : "=r"(h) : "f"(x1), "f"(x0));
    float f0 = __uint_as_float(h << 16);
    float f1 = __uint_as_float(h & 0xFFFF0000u);
    float r0 = x0 - f0, r1 = x1 - f1;
    uint32_t l;
    asm("cvt.rn.bf16x2.f32 %0, %1, %2;" : "=r"(l) : "f"(r1), "f"(r0));
    hi = h; lo = l;
}

__device__ __forceinline__ void mma_bf16(float c[4], const uint32_t a[4],
                                         const uint32_t b[2]) {
    asm volatile(
        "mma.sync.aligned.m16n8k16.row.col.f32.bf16.bf16.f32 "
        "{%0,%1,%2,%3}, {%4,%5,%6,%7}, {%8,%9}, {%0,%1,%2,%3};"
        : "+f"(c[0]), "+f"(c[1]), "+f"(c[2]), "+f"(c[3])
        : "r"(a[0]), "r"(a[1]), "r"(a[2]), "r"(a[3]), "r"(b[0]), "r"(b[1]));
}

__device__ __forceinline__ float warpSum(float v) {
    #pragma unroll
    for (int o = 16; o; o >>= 1) v += __shfl_xor_sync(0xffffffffu, v, o);
    return v;
}
__device__ __forceinline__ float warpMax(float v) {
    #pragma unroll
    for (int o = 16; o; o >>= 1) v = fmaxf(v, __shfl_xor_sync(0xffffffffu, v, o));
    return v;
}
template <bool ISMAX>
__device__ __forceinline__ float blockReduce(float v) {
    __shared__ float sh[8];
    int lane = threadIdx.x & 31, w = threadIdx.x >> 5;
    v = ISMAX ? warpMax(v) : warpSum(v);
    if (lane == 0) sh[w] = v;
    __syncthreads();
    if (w == 0) {
        float t = (lane < 8) ? sh[lane] : (ISMAX ? -INFINITY : 0.0f);
        t = ISMAX ? warpMax(t) : warpSum(t);
        if (lane == 0) sh[0] = t;
    }
    __syncthreads();
    float r = sh[0];
    __syncthreads();
    return r;
}

// ------- bf16x3 mma.sync GEMM, fp32 in/out (NT, 128x128 CTA, 64x32 warp) -----
enum { M_DIV = 0, M_Q = 1, M_K = 2, M_V = 3, M_SIM = 4, M_CTX = 5, M_OUT2 = 6, M_FIN = 7 };

__global__ void __launch_bounds__(THREADS, 1)
k_mma(int mode, const float* __restrict__ pA, const float* __restrict__ pB,
      float* __restrict__ pC) {
    extern __shared__ uint32_t sm[];
    const int tid = threadIdx.x, w = tid >> 5, lane = tid & 31;
    const int wr = w >> 2, wc = w & 3;              // warp grid 2x4
    const int gid = lane >> 2, t4 = lane & 3;       // fragment coords

    // ---- per-mode problem setup (identical to R10) ----
    const float *A, *B;
    float* C = nullptr;
    int K, lda, ldb, ldc = 0;
    const int z = blockIdx.z, bi = z >> 2, bj = z & 3;
    switch (mode) {
        case M_DIV:
            A = g_xu + (size_t)z * TB_ * D_; B = A;
            C = g_div[z]; K = D_; lda = ldb = D_; ldc = TB_; break;
        case M_Q: case M_K: case M_V:
            A = pA; B = pB;
            C = (mode == M_Q) ? g_Q : (mode == M_K) ? g_K : g_V;
            K = D_; lda = ldb = D_; ldc = D_; break;
        case M_SIM:
            A = g_Q + (size_t)(bi * TB_) * D_ + bj * WB_;
            B = g_K + (size_t)(bi * TB_) * D_ + bj * WB_;
            C = g_attw[z]; K = WB_; lda = ldb = D_; ldc = TB_; break;
        case M_CTX:
            A = g_attw[z]; B = g_Vt[z];
            C = g_ctx[z]; K = TB_; lda = TB_; ldb = TB_; ldc = WB_; break;
        case M_OUT2:
            A = g_ctx[z]; B = g_W2;
            K = WB_; lda = WB_; ldb = WB_; break;
        default: // M_FIN
            A = g_y; B = pB; C = pC; K = D_; lda = ldb = D_; ldc = D_; break;
    }
    const int m0 = blockIdx.y * MT, n0 = blockIdx.x * NT;
    A += (size_t)m0 * lda;
    B += (size_t)n0 * ldb;

    // ---- loader mapping: 4 float4 per operand per chunk (as R10) ----
    const float* pa[4];
    const float* pb[4];
    int soff[4];
    #pragma unroll
    for (int p = 0; p < 4; p++) {
        int pos = tid + p * THREADS;        // 0..1023
        int r = pos >> 3, c4 = (pos & 7) << 2;
        soff[p] = r * TW + (c4 >> 1);       // word offset (even)
        pa[p] = A + (size_t)r * lda + c4;
        pb[p] = B + (size_t)r * ldb + c4;
    }

    float acc[4][4][4] = {};
    const int nChunks = K / KC;

    float4 ra[4], rb[4];
    #pragma unroll
    for (int p = 0; p < 4; p++) { ra[p] = *(const float4*)(pa[p]); rb[p] = *(const float4*)(pb[p]); }

    // split + store stage 0
    {
        uint32_t* b0 = sm;
        #pragma unroll
        for (int p = 0; p < 4; p++) {
            uint32_t h0, l0, h1, l1;
            bsplit(ra[p].x, ra[p].y, h0, l0);
            bsplit(ra[p].z, ra[p].w, h1, l1);
            *(uint2*)(b0 + soff[p])          = make_uint2(h0, h1);
            *(uint2*)(b0 + TILEW + soff[p])  = make_uint2(l0, l1);
            bsplit(rb[p].x, rb[p].y, h0, l0);
            bsplit(rb[p].z, rb[p].w, h1, l1);
            *(uint2*)(b0 + 2 * TILEW + soff[p]) = make_uint2(h0, h1);
            *(uint2*)(b0 + 3 * TILEW + soff[p]) = make_uint2(l0, l1);
        }
    }
    __syncthreads();

    // fragment row/col word offsets (constant across chunks)
    const int ar0 = (wr * 64 + gid) * TW;            // + mi*16*TW
    const int br0 = (wc * 32 + gid) * TW;            // + ni*8*TW

    for (int ch = 0; ch < nChunks; ch++) {
        // gmem prefetch for next chunk (long-latency, issued first)
        if (ch + 1 < nChunks) {
            #pragma unroll
            for (int p = 0; p < 4; p++) {
                ra[p] = *(const float4*)(pa[p] + (ch + 1) * KC);
                rb[p] = *(const float4*)(pb[p] + (ch + 1) * KC);
            }
        }
        {
            const uint32_t* base = sm + (ch & 1) * STAGEW;
            const uint32_t* Ahs = base;
            const uint32_t* Als = base + TILEW;
            const uint32_t* Bhs = base + 2 * TILEW;
            const uint32_t* Bls = base + 3 * TILEW;

            // -------- issue ALL fragment loads (phase0 + phase1) up front ----
            // phase0: k-words t4, t4+4 ; phase1: +8
            uint32_t ah0[4][4], al0[4][4], bh0[4][2], bl0[4][2];
            uint32_t ah1[4][4], al1[4][4], bh1[4][2], bl1[4][2];
            const int c0 = t4, c1 = t4 + 4, c2 = t4 + 8, c3 = t4 + 12;
            #pragma unroll
            for (int mi = 0; mi < 4; mi++) {
                const int r0 = ar0 + mi * 16 * TW;
                const int r8 = r0 + 8 * TW;
                ah0[mi][0] = Ahs[r0 + c0]; ah0[mi][1] = Ahs[r8 + c0];
                ah0[mi][2] = Ahs[r0 + c1]; ah0[mi][3] = Ahs[r8 + c1];
                al0[mi][0] = Als[r0 + c0]; al0[mi][1] = Als[r8 + c0];
                al0[mi][2] = Als[r0 + c1]; al0[mi][3] = Als[r8 + c1];
                ah1[mi][0] = Ahs[r0 + c2]; ah1[mi][1] = Ahs[r8 + c2];
                ah1[mi][2] = Ahs[r0 + c3]; ah1[mi][3] = Ahs[r8 + c3];
                al1[mi][0] = Als[r0 + c2]; al1[mi][1] = Als[r8 + c2];
                al1[mi][2] = Als[r0 + c3]; al1[mi][3] = Als[r8 + c3];
            }
            #pragma unroll
            for (int ni = 0; ni < 4; ni++) {
                const int nr = br0 + ni * 8 * TW;
                bh0[ni][0] = Bhs[nr + c0]; bh0[ni][1] = Bhs[nr + c1];
                bl0[ni][0] = Bls[nr + c0]; bl0[ni][1] = Bls[nr + c1];
                bh1[ni][0] = Bhs[nr + c2]; bh1[ni][1] = Bhs[nr + c3];
                bl1[ni][0] = Bls[nr + c2]; bl1[ni][1] = Bls[nr + c3];
            }
            // -------- mma phase0 (overlaps phase1 LDS still in flight) -------
            #pragma unroll
            for (int mi = 0; mi < 4; mi++)
                #pragma unroll
                for (int ni = 0; ni < 4; ni++) {
                    mma_bf16(acc[mi][ni], ah0[mi], bl0[ni]);
                    mma_bf16(acc[mi][ni], al0[mi], bh0[ni]);
                    mma_bf16(acc[mi][ni], ah0[mi], bh0[ni]);
                }
            // -------- mma phase1 ---------------------------------------------
            #pragma unroll
            for (int mi = 0; mi < 4; mi++)
                #pragma unroll
                for (int ni = 0; ni < 4; ni++) {
                    mma_bf16(acc[mi][ni], ah1[mi], bl1[ni]);
                    mma_bf16(acc[mi][ni], al1[mi], bh1[ni]);
                    mma_bf16(acc[mi][ni], ah1[mi], bh1[ni]);
                }
        }
        if (ch + 1 < nChunks) {
            uint32_t* b0 = sm + ((ch + 1) & 1) * STAGEW;
            #pragma unroll
            for (int p = 0; p < 4; p++) {
                uint32_t h0, l0, h1, l1;
                bsplit(ra[p].x, ra[p].y, h0, l0);
                bsplit(ra[p].z, ra[p].w, h1, l1);
                *(uint2*)(b0 + soff[p])          = make_uint2(h0, h1);
                *(uint2*)(b0 + TILEW + soff[p])  = make_uint2(l0, l1);
                bsplit(rb[p].x, rb[p].y, h0, l0);
                bsplit(rb[p].z, rb[p].w, h1, l1);
                *(uint2*)(b0 + 2 * TILEW + soff[p]) = make_uint2(h0, h1);
                *(uint2*)(b0 + 3 * TILEW + soff[p]) = make_uint2(l0, l1);
            }
            __syncthreads();
        }
    }

    // ---- epilogue (identical to R10) ----
    #pragma unroll
    for (int mi = 0; mi < 4; mi++) {
        const int mr0 = m0 + wr * 64 + mi * 16 + gid;
        const int mr1 = mr0 + 8;
        float e0 = 0.f, e1 = 0.f, d0 = 0.f, d1 = 0.f;
        if (mode == M_OUT2) {
            e0 = g_ent[z][mr0]; e1 = g_ent[z][mr1];
            d0 = g_dep[z][mr0]; d1 = g_dep[z][mr1];
        }
        #pragma unroll
        for (int ni = 0; ni < 4; ni++) {
            const int nc = n0 + wc * 32 + ni * 8 + 2 * t4;
            float v00 = acc[mi][ni][0], v01 = acc[mi][ni][1];
            float v10 = acc[mi][ni][2], v11 = acc[mi][ni][3];
            if (mode == M_DIV) {
                v00 = 1.0f - v00; v01 = 1.0f - v01;
                v10 = 1.0f - v10; v11 = 1.0f - v11;
            } else if (mode == M_SIM) {
                v00 += g_AP[(size_t)mr0 * TB_ + nc];
                v01 += g_AP[(size_t)mr0 * TB_ + nc + 1];
                v10 += g_AP[(size_t)mr1 * TB_ + nc];
                v11 += g_AP[(size_t)mr1 * TB_ + nc + 1];
            }
            if (mode == M_OUT2) {
                const float we0 = g_w2e[nc], we1 = g_w2e[nc + 1];
                const float wd0 = g_w2d[nc], wd1 = g_w2d[nc + 1];
                float* y0 = g_y + (size_t)(bi * TB_ + mr0) * D_ + bj * WB_ + nc;
                float* y1 = g_y + (size_t)(bi * TB_ + mr1) * D_ + bj * WB_ + nc;
                y0[0] = v00 + e0 * we0 + d0 * wd0;
                y0[1] = v01 + e0 * we1 + d0 * wd1;
                y1[0] = v10 + e1 * we0 + d1 * wd0;
                y1[1] = v11 + e1 * we1 + d1 * wd1;
            } else {
                float* c0p = C + (size_t)mr0 * ldc + nc;
                float* c1p = C + (size_t)mr1 * ldc + nc;
                *(float2*)c0p = make_float2(v00, v01);
                *(float2*)c1p = make_float2(v10, v11);
            }
        }
    }
}

// ---------------- elementwise stage kernels (identical to R10) ---------------
__global__ void k_norm(const float* __restrict__ x) {
    int t = blockIdx.x, tid = threadIdx.x;
    const float* xp = x + (size_t)t * D_;
    float v = 0.0f;
    for (int j = tid; j < D_; j += 256) { float a = xp[j]; v += a * a; }
    v = blockReduce<false>(v);
    float inv = 1.0f / fmaxf(sqrtf(v), 1e-12f);
    for (int j = tid; j < D_; j += 256) g_xu[(size_t)t * D_ + j] = xp[j] * inv;
}

__global__ void k_ap() {
    int idx = blockIdx.x * 256 + threadIdx.x;
    int p = idx >> 10, c = idx & 1023;
    int ih = c >> 1;
    float ang = (float)p / powf(10000.0f, (2.0f * (float)ih) / 1024.0f);
    g_AP[idx] = (c & 1) ? cosf(ang) : sinf(ang);
}

__global__ void k_repack(const float* __restrict__ W2) {
    int idx = blockIdx.x * 256 + threadIdx.x;
    if (idx >= WB_ * (WB_ + 2)) return;
    int n = idx / (WB_ + 2), k = idx % (WB_ + 2);
    float v = W2[idx];
    if (k < WB_)       g_W2[n * WB_ + k] = v;
    else if (k == WB_) g_w2e[n] = v;
    else               g_w2d[n] = v;
}

__global__ void k_softmax() {
    int row = blockIdx.x;
    int b = row >> 10, q = row & 1023;
    int i = b >> 2;
    int tid = threadIdx.x;
    float* sp = g_attw[b] + (size_t)q * TB_;
    const float* dv = g_div[i] + (size_t)q * TB_;
    float s[4], d[4];
    #pragma unroll
    for (int j = 0; j < 4; j++) { s[j] = sp[tid + j * 256]; d[j] = dv[tid + j * 256]; }
    float mx = fmaxf(fmaxf(s[0], s[1]), fmaxf(s[2], s[3]));
    mx = blockReduce<true>(mx);
    float e[4], Z = 0.f, t = 0.f, ww = 0.f, ds = 0.f;
    #pragma unroll
    for (int j = 0; j < 4; j++) {
        e[j] = __expf(s[j] - mx);
        Z += e[j]; t += e[j] * (s[j] - mx); ww += d[j] * e[j]; ds += d[j];
    }
    Z = blockReduce<false>(Z);
    t = blockReduce<false>(t);
    ww = blockReduce<false>(ww);
    ds = blockReduce<false>(ds);
    float invZ = 1.0f / Z;
    #pragma unroll
    for (int j = 0; j < 4; j++) sp[tid + j * 256] = e[j] * invZ;
    if (tid == 0) {
        g_ent[b][q] = (logf(Z) - t * invZ) * (1.0f / 6.931471805599453f);
        g_dep[b][q] = (ww * invZ) / ds;
    }
}

__global__ void k_entnorm() {
    int b = blockIdx.x, tid = threadIdx.x;
    float v = 0.0f;
    for (int j = tid; j < TB_; j += 256) v += fabsf(g_ent[b][j]);
    v = blockReduce<false>(v);
    float inv = 1.0f / fmaxf(v, 1e-12f);
    for (int j = tid; j < TB_; j += 256) g_ent[b][j] *= inv;
}

// Vt[b][n][k] = V[(i*TB+k)*D + j*WB+n] * (1 + dep[b][k])
__global__ void k_vt() {
    __shared__ float tile[32][33];
    int b = blockIdx.z, i = b >> 2, j = b & 3;
    int k0 = blockIdx.x * 32, n0 = blockIdx.y * 32;
    int tx = threadIdx.x, ty = threadIdx.y;    // 32 x 8
    #pragma unroll
    for (int dy = 0; dy < 4; dy++) {
        int k = k0 + ty + dy * 8;
        int n = n0 + tx;
        tile[ty + dy * 8][tx] =
            g_V[(size_t)(i * TB_ + k) * D_ + j * WB_ + n] * (1.0f + g_dep[b][k]);
    }
    __syncthreads();
    #pragma unroll
    for (int dy = 0; dy < 4; dy++) {
        int n = n0 + ty + dy * 8;
        int k = k0 + tx;
        g_Vt[b][(size_t)n * TB_ + k] = tile[tx][ty + dy * 8];
    }
}

// ---------------- launch (identical to R10) ----------------------------------
extern "C" void kernel_launch(void* const* d_in, const int* in_sizes, int n_in,
                              void* d_out, int out_size) {
    const float* x    = (const float*)d_in[0];
    const float* Wq   = (const float*)d_in[1];
    const float* Wk   = (const float*)d_in[2];
    const float* Wv   = (const float*)d_in[3];
    const float* Wout = (const float*)d_in[4];
    const float* W2   = (const float*)d_in[5];
    float* out = (float*)d_out;

    cudaFuncSetAttribute(k_mma, cudaFuncAttributeMaxDynamicSharedMemorySize, SMEM_DYN);

    k_norm<<<T_, 256>>>(x);
    k_ap<<<(TB_ * TB_) / 256, 256>>>();
    k_repack<<<(WB_ * (WB_ + 2) + 255) / 256, 256>>>(W2);

    k_mma<<<dim3(TB_ / NT, TB_ / MT, S_), THREADS, SMEM_DYN>>>(M_DIV, nullptr, nullptr, nullptr);

    k_mma<<<dim3(D_ / NT, T_ / MT, 1), THREADS, SMEM_DYN>>>(M_Q, x, Wq, nullptr);
    k_mma<<<dim3(D_ / NT, T_ / MT, 1), THREADS, SMEM_DYN>>>(M_K, x, Wk, nullptr);
    k_mma<<<dim3(D_ / NT, T_ / MT, 1), THREADS, SMEM_DYN>>>(M_V, x, Wv, nullptr);

    k_mma<<<dim3(TB_ / NT, TB_ / MT, NB_), THREADS, SMEM_DYN>>>(M_SIM, nullptr, nullptr, nullptr);

    k_softmax<<<NB_ * TB_, 256>>>();
    k_entnorm<<<NB_, 256>>>();
    k_vt<<<dim3(TB_ / 32, WB_ / 32, NB_), dim3(32, 8)>>>();

    k_mma<<<dim3(WB_ / NT, TB_ / MT, NB_), THREADS, SMEM_DYN>>>(M_CTX, nullptr, nullptr, nullptr);
    k_mma<<<dim3(WB_ / NT, TB_ / MT, NB_), THREADS, SMEM_DYN>>>(M_OUT2, nullptr, nullptr, nullptr);
    k_mma<<<dim3(D_ / NT, T_ / MT, 1), THREADS, SMEM_DYN>>>(M_FIN, nullptr, Wout, out);
}